// round 1
// baseline (speedup 1.0000x reference)
#include <cuda_runtime.h>
#include <math.h>

// Problem constants
#define BN   4096          // batch
#define TT   8             // tuple length / steps
#define HH   512           // hidden
#define NG   2048          // 4*H gates

// ---------------- device scratch (no allocations allowed) ----------------
__device__ float g_P[(size_t)BN * 9 * NG];      // precomputed input-side gates, row (b*9+t), t=8 => conv row
__device__ float g_W1E[(size_t)BN * TT * HH];   // W1 @ E + b1
__device__ float g_inp0[(size_t)BN * HH];       // conv output
__device__ float g_Wr [(size_t)NG * HH];        // Wih reordered rows: n = 4*j+g
__device__ float g_Whr[(size_t)NG * HH];        // Whh reordered
__device__ float g_brb[NG];                     // bih+bhh reordered
__device__ float g_c  [(size_t)BN * HH];
__device__ float g_hA [(size_t)BN * HH];        // h double buffer
__device__ float g_hB [(size_t)BN * HH];
__device__ int   g_sel [BN];                    // which P row feeds current step (8 = conv row)
__device__ int   g_mask[BN];                    // visited-pointer bitmask

__device__ __forceinline__ float sigm(float x) { return 1.0f / (1.0f + expf(-x)); }

// ---------------- prep: reorder LSTM weights so gate quads are contiguous ----------------
__global__ void prep_k(const float* __restrict__ Wih, const float* __restrict__ Whh,
                       const float* __restrict__ bih, const float* __restrict__ bhh) {
    int idx = blockIdx.x * blockDim.x + threadIdx.x;   // over NG*HH
    int n = idx >> 9, k = idx & 511;
    int j = n >> 2, g = n & 3;
    int src = (g * 512 + j) * 512 + k;
    g_Wr[idx]  = Wih[src];
    g_Whr[idx] = Whh[src];
    if (k == 0) g_brb[n] = bih[g * 512 + j] + bhh[g * 512 + j];
}

// ---------------- conv: inp0[b,h] = sum_t enc[b,t,h]*cw[t] + cb ----------------
__global__ void conv_k(const float* __restrict__ enc, const float* __restrict__ cw,
                       const float* __restrict__ cb) {
    int idx = blockIdx.x * blockDim.x + threadIdx.x;   // over BN*HH
    int b = idx >> 9, hh = idx & 511;
    const float* e = enc + (size_t)b * TT * HH + hh;
    float s = cb[0];
#pragma unroll
    for (int t = 0; t < TT; t++) s += e[t * HH] * cw[t];
    g_inp0[idx] = s;
}

// ---------------- init: zero state ----------------
__global__ void init_k() {
    int idx = blockIdx.x * blockDim.x + threadIdx.x;   // over BN*HH
    g_c[idx] = 0.0f;
    g_hA[idx] = 0.0f;
    if (idx < BN) { g_sel[idx] = 8; g_mask[idx] = 0; }
}

// ---------------- fp32 SIMT GEMM: Out[m,n] = sum_k A[m,k]*W[n,k] ----------------
// 128x128 block tile, K-tile 16, 256 threads, 8x8 per thread.
// EPI==0: Out[dstrow(m)*ldo + n] = acc + bias[n], dstrow = (m/grp)*rowmul + m%grp + rowoff
// EPI==1: fused LSTM cell: gates = acc + P[(b*9+sel[b])*NG + n], update c, write h
template <int EPI>
__global__ void __launch_bounds__(256, 2)
gemm_k(const float* __restrict__ A, int lda,
       const float* __restrict__ W,
       const float* __restrict__ bias,
       float* __restrict__ Out, int ldo, int K,
       int grp, int rowmul, int rowoff,
       float* __restrict__ hout) {
    __shared__ float As[16][132];
    __shared__ float Bs[16][132];
    int tid = threadIdx.x;
    int m0 = blockIdx.y * 128, n0 = blockIdx.x * 128;
    int tx = tid & 15, ty = tid >> 4;

    float acc[8][8];
#pragma unroll
    for (int i = 0; i < 8; i++)
#pragma unroll
        for (int j = 0; j < 8; j++) acc[i][j] = 0.0f;

    for (int k0 = 0; k0 < K; k0 += 16) {
#pragma unroll
        for (int r = 0; r < 2; r++) {
            int q = tid + r * 256;          // 512 quads per tile
            int mm = q >> 2, kq = (q & 3) * 4;
            float4 av = *(const float4*)(A + (size_t)(m0 + mm) * lda + k0 + kq);
            As[kq + 0][mm] = av.x; As[kq + 1][mm] = av.y;
            As[kq + 2][mm] = av.z; As[kq + 3][mm] = av.w;
            float4 wv = *(const float4*)(W + (size_t)(n0 + mm) * K + k0 + kq);
            Bs[kq + 0][mm] = wv.x; Bs[kq + 1][mm] = wv.y;
            Bs[kq + 2][mm] = wv.z; Bs[kq + 3][mm] = wv.w;
        }
        __syncthreads();
#pragma unroll
        for (int kk = 0; kk < 16; kk++) {
            float a[8], bb[8];
            *(float4*)(a)      = *(const float4*)&As[kk][ty * 8];
            *(float4*)(a + 4)  = *(const float4*)&As[kk][ty * 8 + 4];
            *(float4*)(bb)     = *(const float4*)&Bs[kk][tx * 8];
            *(float4*)(bb + 4) = *(const float4*)&Bs[kk][tx * 8 + 4];
#pragma unroll
            for (int i = 0; i < 8; i++)
#pragma unroll
                for (int j = 0; j < 8; j++) acc[i][j] += a[i] * bb[j];
        }
        __syncthreads();
    }

    if (EPI == 0) {
#pragma unroll
        for (int i = 0; i < 8; i++) {
            int r = m0 + ty * 8 + i;
            int dr = (r / grp) * rowmul + (r % grp) + rowoff;
            float* op = Out + (size_t)dr * ldo + n0 + tx * 8;
            const float* bp = bias + n0 + tx * 8;
#pragma unroll
            for (int j = 0; j < 8; j++) op[j] = acc[i][j] + bp[j];
        }
    } else {
#pragma unroll
        for (int i = 0; i < 8; i++) {
            int b = m0 + ty * 8 + i;
            int s = g_sel[b];
            const float* Pr = g_P + ((size_t)b * 9 + s) * NG + n0 + tx * 8;
#pragma unroll
            for (int q = 0; q < 2; q++) {
                float gi = acc[i][4 * q + 0] + Pr[4 * q + 0];
                float gf = acc[i][4 * q + 1] + Pr[4 * q + 1];
                float gg = acc[i][4 * q + 2] + Pr[4 * q + 2];
                float go = acc[i][4 * q + 3] + Pr[4 * q + 3];
                int hidx = (n0 + tx * 8 + 4 * q) >> 2;
                float co = g_c[(size_t)b * HH + hidx];
                float cn = sigm(gf) * co + sigm(gi) * tanhf(gg);
                float hv = sigm(go) * tanhf(cn);
                g_c[(size_t)b * HH + hidx] = cn;
                hout[(size_t)b * HH + hidx] = hv;
            }
        }
    }
}

// ---------------- fused attention step: hW2 matvec + Ui + argmax + mask/sel ----------------
__global__ void attn_k(const float* __restrict__ h,
                       const float* __restrict__ W2, const float* __restrict__ b2,
                       const float* __restrict__ vw, const float* __restrict__ vb,
                       float* __restrict__ probs, float* __restrict__ ptrs, int step) {
    __shared__ float hs[HH];
    __shared__ float red[8][16];
    __shared__ float ui[8];
    int b = blockIdx.x, o = threadIdx.x;
    hs[o] = h[(size_t)b * HH + o];
    __syncthreads();

    // hW2[b,o] = b2[o] + sum_k W2[o,k]*h[b,k]
    float a0 = 0.f, a1 = 0.f, a2 = 0.f, a3 = 0.f;
    const float4* w4 = (const float4*)(W2 + (size_t)o * HH);
    const float4* h4 = (const float4*)hs;
#pragma unroll 8
    for (int kq = 0; kq < HH / 4; kq++) {
        float4 w = w4[kq];
        float4 hv = h4[kq];
        a0 += w.x * hv.x; a1 += w.y * hv.y; a2 += w.z * hv.z; a3 += w.w * hv.w;
    }
    float hw2 = b2[o] + ((a0 + a1) + (a2 + a3));

    float tw = vw[o];
    float part[8];
    const float* we = g_W1E + (size_t)b * TT * HH + o;
#pragma unroll
    for (int t = 0; t < TT; t++) part[t] = tw * tanhf(we[t * HH] + hw2);

    // deterministic reduction: warp shuffle, then 16 partials summed by one thread per t
#pragma unroll
    for (int off = 16; off > 0; off >>= 1)
#pragma unroll
        for (int t = 0; t < TT; t++) part[t] += __shfl_down_sync(0xffffffffu, part[t], off);
    if ((o & 31) == 0) {
        int w = o >> 5;
#pragma unroll
        for (int t = 0; t < TT; t++) red[t][w] = part[t];
    }
    __syncthreads();
    if (o < TT) {
        float s = 0.f;
#pragma unroll
        for (int w = 0; w < 16; w++) s += red[o][w];
        s += vb[0];
        ui[o] = s;
        probs[(size_t)b * (TT * TT) + step * TT + o] = s;   // Ui is stored pre-softmax
    }
    __syncthreads();
    if (o == 0) {
        // softmax is monotone -> argmax of masked softmax == argmax of Ui over unmasked
        int m = g_mask[b];
        int best = 0;
        float bv = -3.4e38f;
#pragma unroll
        for (int t = 0; t < TT; t++) {
            bool ok = ((m >> t) & 1) == 0;
            if (ok && ui[t] > bv) { bv = ui[t]; best = t; }
        }
        g_mask[b] = m | (1 << best);
        g_sel[b] = best;
        ptrs[(size_t)b * TT + step] = (float)best;
    }
}

// ---------------- launch ----------------
extern "C" void kernel_launch(void* const* d_in, const int* in_sizes, int n_in,
                              void* d_out, int out_size) {
    const float* inps   = (const float*)d_in[0];
    const float* enc    = (const float*)d_in[1];
    const float* conv_w = (const float*)d_in[2];
    const float* conv_b = (const float*)d_in[3];
    const float* Wih    = (const float*)d_in[4];
    const float* Whh    = (const float*)d_in[5];
    const float* bih    = (const float*)d_in[6];
    const float* bhh    = (const float*)d_in[7];
    const float* W1     = (const float*)d_in[8];
    const float* b1     = (const float*)d_in[9];
    const float* W2     = (const float*)d_in[10];
    const float* b2     = (const float*)d_in[11];
    const float* vw     = (const float*)d_in[12];
    const float* vb     = (const float*)d_in[13];

    float* probs = (float*)d_out;                       // [B, T, T]
    float* ptrs  = probs + (size_t)BN * TT * TT;        // [B, T]

    void *pP, *pW1E, *pinp0, *pWr, *pWhr, *pbrb, *phA, *phB;
    cudaGetSymbolAddress(&pP,    g_P);
    cudaGetSymbolAddress(&pW1E,  g_W1E);
    cudaGetSymbolAddress(&pinp0, g_inp0);
    cudaGetSymbolAddress(&pWr,   g_Wr);
    cudaGetSymbolAddress(&pWhr,  g_Whr);
    cudaGetSymbolAddress(&pbrb,  g_brb);
    cudaGetSymbolAddress(&phA,   g_hA);
    cudaGetSymbolAddress(&phB,   g_hB);

    prep_k<<<(NG * HH) / 256, 256>>>(Wih, Whh, bih, bhh);
    conv_k<<<(BN * HH) / 256, 256>>>(enc, conv_w, conv_b);
    init_k<<<(BN * HH) / 256, 256>>>();

    // W1E = enc @ W1^T + b1   (M=32768, N=512, K=512), rows map 1:1
    {
        dim3 g(HH / 128, (BN * TT) / 128);
        gemm_k<0><<<g, 256>>>(enc, HH, W1, b1, (float*)pW1E, HH, HH, 1, 1, 0, nullptr);
    }
    // P[b,t] = inps[b,t] @ Wr^T + brb   (M=32768, N=2048), dst row = (r/8)*9 + r%8
    {
        dim3 g(NG / 128, (BN * TT) / 128);
        gemm_k<0><<<g, 256>>>(inps, HH, (const float*)pWr, (const float*)pbrb,
                              (float*)pP, NG, HH, 8, 9, 0, nullptr);
    }
    // P[b,8] = inp0 @ Wr^T + brb   (M=4096), dst row = r*9 + 8
    {
        dim3 g(NG / 128, BN / 128);
        gemm_k<0><<<g, 256>>>((const float*)pinp0, HH, (const float*)pWr, (const float*)pbrb,
                              (float*)pP, NG, HH, 1, 9, 8, nullptr);
    }

    // 8 decode steps: GEMM(h@Whr^T)+LSTM-cell fused, then attention+argmax
    for (int s = 0; s < TT; s++) {
        const float* hin = (s & 1) ? (const float*)phB : (const float*)phA;
        float* hout      = (s & 1) ? (float*)phA : (float*)phB;
        dim3 g(NG / 128, BN / 128);
        gemm_k<1><<<g, 256>>>(hin, HH, (const float*)pWhr, nullptr,
                              nullptr, 0, HH, 1, 1, 0, hout);
        attn_k<<<BN, HH>>>(hout, W2, b2, vw, vb, probs, ptrs, s);
    }
}

// round 2
// speedup vs baseline: 2.6949x; 2.6949x over previous
#include <cuda_runtime.h>
#include <math.h>

// Problem constants
#define BN   4096          // batch
#define TT   8             // tuple length / steps
#define HH   512           // hidden
#define NG   2048          // 4*H gates

// ---------------- device scratch (no allocations allowed) ----------------
__device__ float g_P[(size_t)BN * 9 * NG];      // precomputed input-side gates, row (b*9+t), t=8 => conv row
__device__ float g_W1E[(size_t)BN * TT * HH];   // W1 @ E + b1
__device__ float g_inp0[(size_t)BN * HH];       // conv output
__device__ float g_Wr [(size_t)NG * HH];        // Wih reordered rows: n = 4*j+g
__device__ float g_Whr[(size_t)NG * HH];        // Whh reordered
__device__ float g_brb[NG];                     // bih+bhh reordered
__device__ float g_c  [(size_t)BN * HH];
__device__ float g_hA [(size_t)BN * HH];        // h double buffer
__device__ float g_hB [(size_t)BN * HH];
__device__ float g_hw2[(size_t)BN * HH];        // h @ W2^T + b2
__device__ int   g_sel [BN];                    // which P row feeds current step (8 = conv row)
__device__ int   g_mask[BN];                    // visited-pointer bitmask

__device__ __forceinline__ float sigm(float x) { return 1.0f / (1.0f + expf(-x)); }

// ---- packed f32x2 helpers (sm_100 PTX; ptxas never auto-emits FFMA2) ----
__device__ __forceinline__ unsigned long long pack2(float x) {
    unsigned long long r;
    unsigned u = __float_as_uint(x);
    asm("mov.b64 %0, {%1, %1};" : "=l"(r) : "r"(u));
    return r;
}
__device__ __forceinline__ void fma2(unsigned long long& d,
                                     unsigned long long a, unsigned long long b) {
    asm("fma.rn.f32x2 %0, %1, %2, %0;" : "+l"(d) : "l"(a), "l"(b));
}
__device__ __forceinline__ float lo32(unsigned long long v) {
    return __uint_as_float((unsigned)(v & 0xffffffffull));
}
__device__ __forceinline__ float hi32(unsigned long long v) {
    return __uint_as_float((unsigned)(v >> 32));
}

// ---------------- prep: reorder LSTM weights so gate quads are contiguous ----------------
__global__ void prep_k(const float* __restrict__ Wih, const float* __restrict__ Whh,
                       const float* __restrict__ bih, const float* __restrict__ bhh) {
    int idx = blockIdx.x * blockDim.x + threadIdx.x;   // over NG*HH
    int n = idx >> 9, k = idx & 511;
    int j = n >> 2, g = n & 3;
    int src = (g * 512 + j) * 512 + k;
    g_Wr[idx]  = Wih[src];
    g_Whr[idx] = Whh[src];
    if (k == 0) g_brb[n] = bih[g * 512 + j] + bhh[g * 512 + j];
}

// ---------------- conv: inp0[b,h] = sum_t enc[b,t,h]*cw[t] + cb ----------------
__global__ void conv_k(const float* __restrict__ enc, const float* __restrict__ cw,
                       const float* __restrict__ cb) {
    int idx = blockIdx.x * blockDim.x + threadIdx.x;   // over BN*HH
    int b = idx >> 9, hh = idx & 511;
    const float* e = enc + (size_t)b * TT * HH + hh;
    float s = cb[0];
#pragma unroll
    for (int t = 0; t < TT; t++) s += e[t * HH] * cw[t];
    g_inp0[idx] = s;
}

// ---------------- init: zero state ----------------
__global__ void init_k() {
    int idx = blockIdx.x * blockDim.x + threadIdx.x;   // over BN*HH
    g_c[idx] = 0.0f;
    g_hA[idx] = 0.0f;
    if (idx < BN) { g_sel[idx] = 8; g_mask[idx] = 0; }
}

// ---------------- fp32 SIMT GEMM with packed FFMA2 + double-buffered smem ----------------
// Out[m,n] = sum_k A[m,k]*W[n,k]
// 128x128 block tile, K-tile 16, 256 threads, 8x8 per thread (as 8x4 f32x2 pairs).
// EPI==0: Out[dstrow(m)*ldo + n] = acc + bias[n], dstrow = (m/grp)*rowmul + m%grp + rowoff
// EPI==1: fused LSTM cell: gates = acc + P[(b*9+sel[b])*NG + n], update c, write h
template <int EPI>
__global__ void __launch_bounds__(256, 2)
gemm_k(const float* __restrict__ A, int lda,
       const float* __restrict__ W,
       const float* __restrict__ bias,
       float* __restrict__ Out, int ldo, int K,
       int grp, int rowmul, int rowoff,
       float* __restrict__ hout) {
    __shared__ __align__(16) float As[2][16][132];
    __shared__ __align__(16) float Bs[2][16][132];
    int tid = threadIdx.x;
    int m0 = blockIdx.y * 128, n0 = blockIdx.x * 128;
    int tx = tid & 15, ty = tid >> 4;

    unsigned long long acc[8][4];
#pragma unroll
    for (int i = 0; i < 8; i++)
#pragma unroll
        for (int j = 0; j < 4; j++) acc[i][j] = 0ull;

    // loader coordinates (2 float4-quads per thread per operand tile)
    int qm[2], qk[2];
#pragma unroll
    for (int r = 0; r < 2; r++) {
        int q = tid + r * 256;
        qm[r] = q >> 2;
        qk[r] = (q & 3) * 4;
    }

    int nk = K >> 4;
    // preload k-tile 0
#pragma unroll
    for (int r = 0; r < 2; r++) {
        float4 av = *(const float4*)(A + (size_t)(m0 + qm[r]) * lda + qk[r]);
        As[0][qk[r] + 0][qm[r]] = av.x; As[0][qk[r] + 1][qm[r]] = av.y;
        As[0][qk[r] + 2][qm[r]] = av.z; As[0][qk[r] + 3][qm[r]] = av.w;
        float4 wv = *(const float4*)(W + (size_t)(n0 + qm[r]) * K + qk[r]);
        Bs[0][qk[r] + 0][qm[r]] = wv.x; Bs[0][qk[r] + 1][qm[r]] = wv.y;
        Bs[0][qk[r] + 2][qm[r]] = wv.z; Bs[0][qk[r] + 3][qm[r]] = wv.w;
    }
    __syncthreads();

    int p = 0;
    for (int kt = 0; kt < nk; kt++) {
        float4 av[2], wv[2];
        bool pre = (kt + 1 < nk);
        if (pre) {
            int k0 = (kt + 1) * 16;
#pragma unroll
            for (int r = 0; r < 2; r++) {
                av[r] = *(const float4*)(A + (size_t)(m0 + qm[r]) * lda + k0 + qk[r]);
                wv[r] = *(const float4*)(W + (size_t)(n0 + qm[r]) * K + k0 + qk[r]);
            }
        }
#pragma unroll
        for (int kk = 0; kk < 16; kk++) {
            float a[8];
            *(float4*)(a)     = *(const float4*)&As[p][kk][ty * 8];
            *(float4*)(a + 4) = *(const float4*)&As[p][kk][ty * 8 + 4];
            ulonglong2 q0 = *(const ulonglong2*)&Bs[p][kk][tx * 8];
            ulonglong2 q1 = *(const ulonglong2*)&Bs[p][kk][tx * 8 + 4];
#pragma unroll
            for (int i = 0; i < 8; i++) {
                unsigned long long ap = pack2(a[i]);
                fma2(acc[i][0], ap, q0.x);
                fma2(acc[i][1], ap, q0.y);
                fma2(acc[i][2], ap, q1.x);
                fma2(acc[i][3], ap, q1.y);
            }
        }
        if (pre) {
            int pn = p ^ 1;
#pragma unroll
            for (int r = 0; r < 2; r++) {
                As[pn][qk[r] + 0][qm[r]] = av[r].x; As[pn][qk[r] + 1][qm[r]] = av[r].y;
                As[pn][qk[r] + 2][qm[r]] = av[r].z; As[pn][qk[r] + 3][qm[r]] = av[r].w;
                Bs[pn][qk[r] + 0][qm[r]] = wv[r].x; Bs[pn][qk[r] + 1][qm[r]] = wv[r].y;
                Bs[pn][qk[r] + 2][qm[r]] = wv[r].z; Bs[pn][qk[r] + 3][qm[r]] = wv[r].w;
            }
        }
        __syncthreads();
        p ^= 1;
    }

    if (EPI == 0) {
#pragma unroll
        for (int i = 0; i < 8; i++) {
            int r = m0 + ty * 8 + i;
            int dr = (r / grp) * rowmul + (r % grp) + rowoff;
            float* op = Out + (size_t)dr * ldo + n0 + tx * 8;
            const float* bp = bias + n0 + tx * 8;
#pragma unroll
            for (int j = 0; j < 4; j++) {
                op[2 * j + 0] = lo32(acc[i][j]) + bp[2 * j + 0];
                op[2 * j + 1] = hi32(acc[i][j]) + bp[2 * j + 1];
            }
        }
    } else {
#pragma unroll
        for (int i = 0; i < 8; i++) {
            int b = m0 + ty * 8 + i;
            int s = g_sel[b];
            const float* Pr = g_P + ((size_t)b * 9 + s) * NG + n0 + tx * 8;
#pragma unroll
            for (int q = 0; q < 2; q++) {
                float gi = lo32(acc[i][2 * q + 0]) + Pr[4 * q + 0];
                float gf = hi32(acc[i][2 * q + 0]) + Pr[4 * q + 1];
                float gg = lo32(acc[i][2 * q + 1]) + Pr[4 * q + 2];
                float go = hi32(acc[i][2 * q + 1]) + Pr[4 * q + 3];
                int hidx = (n0 + tx * 8 + 4 * q) >> 2;
                float co = g_c[(size_t)b * HH + hidx];
                float cn = sigm(gf) * co + sigm(gi) * tanhf(gg);
                float hv = sigm(go) * tanhf(cn);
                g_c[(size_t)b * HH + hidx] = cn;
                hout[(size_t)b * HH + hidx] = hv;
            }
        }
    }
}

// ---------------- fused attention step: Ui + argmax + mask/sel (hW2 precomputed by GEMM) ----------------
__global__ void attn_k(const float* __restrict__ hw2,
                       const float* __restrict__ vw, const float* __restrict__ vb,
                       float* __restrict__ probs, float* __restrict__ ptrs, int step) {
    __shared__ float red[8][16];
    __shared__ float ui[8];
    int b = blockIdx.x, o = threadIdx.x;

    float hv = hw2[(size_t)b * HH + o];   // already includes b2
    float tw = vw[o];
    float part[8];
    const float* we = g_W1E + (size_t)b * TT * HH + o;
#pragma unroll
    for (int t = 0; t < TT; t++) part[t] = tw * tanhf(we[t * HH] + hv);

    // deterministic reduction: warp shuffle, then 16 partials summed by one thread per t
#pragma unroll
    for (int off = 16; off > 0; off >>= 1)
#pragma unroll
        for (int t = 0; t < TT; t++) part[t] += __shfl_down_sync(0xffffffffu, part[t], off);
    if ((o & 31) == 0) {
        int w = o >> 5;
#pragma unroll
        for (int t = 0; t < TT; t++) red[t][w] = part[t];
    }
    __syncthreads();
    if (o < TT) {
        float s = 0.f;
#pragma unroll
        for (int w = 0; w < 16; w++) s += red[o][w];
        s += vb[0];
        ui[o] = s;
        probs[(size_t)b * (TT * TT) + step * TT + o] = s;   // Ui is stored pre-softmax
    }
    __syncthreads();
    if (o == 0) {
        // softmax is monotone -> argmax of masked softmax == argmax of Ui over unmasked
        int m = g_mask[b];
        int best = 0;
        float bv = -3.4e38f;
#pragma unroll
        for (int t = 0; t < TT; t++) {
            bool ok = ((m >> t) & 1) == 0;
            if (ok && ui[t] > bv) { bv = ui[t]; best = t; }
        }
        g_mask[b] = m | (1 << best);
        g_sel[b] = best;
        ptrs[(size_t)b * TT + step] = (float)best;
    }
}

// ---------------- launch ----------------
extern "C" void kernel_launch(void* const* d_in, const int* in_sizes, int n_in,
                              void* d_out, int out_size) {
    const float* inps   = (const float*)d_in[0];
    const float* enc    = (const float*)d_in[1];
    const float* conv_w = (const float*)d_in[2];
    const float* conv_b = (const float*)d_in[3];
    const float* Wih    = (const float*)d_in[4];
    const float* Whh    = (const float*)d_in[5];
    const float* bih    = (const float*)d_in[6];
    const float* bhh    = (const float*)d_in[7];
    const float* W1     = (const float*)d_in[8];
    const float* b1     = (const float*)d_in[9];
    const float* W2     = (const float*)d_in[10];
    const float* b2     = (const float*)d_in[11];
    const float* vw     = (const float*)d_in[12];
    const float* vb     = (const float*)d_in[13];

    float* probs = (float*)d_out;                       // [B, T, T]
    float* ptrs  = probs + (size_t)BN * TT * TT;        // [B, T]

    void *pP, *pW1E, *pinp0, *pWr, *pWhr, *pbrb, *phA, *phB, *phw2;
    cudaGetSymbolAddress(&pP,    g_P);
    cudaGetSymbolAddress(&pW1E,  g_W1E);
    cudaGetSymbolAddress(&pinp0, g_inp0);
    cudaGetSymbolAddress(&pWr,   g_Wr);
    cudaGetSymbolAddress(&pWhr,  g_Whr);
    cudaGetSymbolAddress(&pbrb,  g_brb);
    cudaGetSymbolAddress(&phA,   g_hA);
    cudaGetSymbolAddress(&phB,   g_hB);
    cudaGetSymbolAddress(&phw2,  g_hw2);

    prep_k<<<(NG * HH) / 256, 256>>>(Wih, Whh, bih, bhh);
    conv_k<<<(BN * HH) / 256, 256>>>(enc, conv_w, conv_b);
    init_k<<<(BN * HH) / 256, 256>>>();

    // W1E = enc @ W1^T + b1   (M=32768, N=512, K=512), rows map 1:1
    {
        dim3 g(HH / 128, (BN * TT) / 128);
        gemm_k<0><<<g, 256>>>(enc, HH, W1, b1, (float*)pW1E, HH, HH, 1, 1, 0, nullptr);
    }
    // P[b,t] = inps[b,t] @ Wr^T + brb   (M=32768, N=2048), dst row = (r/8)*9 + r%8
    {
        dim3 g(NG / 128, (BN * TT) / 128);
        gemm_k<0><<<g, 256>>>(inps, HH, (const float*)pWr, (const float*)pbrb,
                              (float*)pP, NG, HH, 8, 9, 0, nullptr);
    }
    // P[b,8] = inp0 @ Wr^T + brb   (M=4096), dst row = r*9 + 8
    {
        dim3 g(NG / 128, BN / 128);
        gemm_k<0><<<g, 256>>>((const float*)pinp0, HH, (const float*)pWr, (const float*)pbrb,
                              (float*)pP, NG, HH, 1, 9, 8, nullptr);
    }

    // 8 decode steps: GEMM(h@Whr^T)+LSTM fused, then hW2 GEMM, then attention+argmax
    for (int s = 0; s < TT; s++) {
        const float* hin = (s & 1) ? (const float*)phB : (const float*)phA;
        float* hout      = (s & 1) ? (float*)phA : (float*)phB;
        {
            dim3 g(NG / 128, BN / 128);
            gemm_k<1><<<g, 256>>>(hin, HH, (const float*)pWhr, nullptr,
                                  nullptr, 0, HH, 1, 1, 0, hout);
        }
        {
            dim3 g(HH / 128, BN / 128);
            gemm_k<0><<<g, 256>>>((const float*)hout, HH, W2, b2,
                                  (float*)phw2, HH, HH, 1, 1, 0, nullptr);
        }
        attn_k<<<BN, HH>>>((const float*)phw2, vw, vb, probs, ptrs, s);
    }
}

// round 5
// speedup vs baseline: 4.0235x; 1.4930x over previous
#include <cuda_runtime.h>
#include <cuda_bf16.h>
#include <math.h>
#include <stdint.h>

// Problem constants
#define BN   4096
#define TT   8
#define HH   512
#define NG   2048
#define KK   512                  // inner dim of every GEMM

// plane strides (elements)
#define PS_ENC  ((size_t)32768 * 512)
#define PS_INP0 ((size_t)4096 * 512)
#define PS_W    ((size_t)2048 * 512)
#define PS_W1   ((size_t)512 * 512)
#define PS_H    ((size_t)4096 * 512)

// ---------------- device scratch ----------------
__device__ float g_P[(size_t)BN * 9 * NG];
__device__ float g_W1E[(size_t)BN * TT * HH];
__device__ float g_brb[NG];
__device__ float g_c  [(size_t)BN * HH];
__device__ float g_hw2[(size_t)BN * HH];
__device__ int   g_sel [BN];
__device__ int   g_mask[BN];

// bf16x3 plane arrays: [plane][rows][512]
__device__ __nv_bfloat16 g_encP [3 * PS_ENC];
__device__ __nv_bfloat16 g_inpsP[3 * PS_ENC];
__device__ __nv_bfloat16 g_inp0P[3 * PS_INP0];
__device__ __nv_bfloat16 g_WrP  [3 * PS_W];
__device__ __nv_bfloat16 g_WhrP [3 * PS_W];
__device__ __nv_bfloat16 g_W1P  [3 * PS_W1];
__device__ __nv_bfloat16 g_W2P  [3 * PS_W1];
__device__ __nv_bfloat16 g_hPA  [3 * PS_H];
__device__ __nv_bfloat16 g_hPB  [3 * PS_H];

__device__ __forceinline__ float sigm(float x) { return 1.0f / (1.0f + expf(-x)); }

__device__ __forceinline__ uint32_t smem_to_u32(const void* p) {
    uint32_t a;
    asm("{ .reg .u64 t; cvta.to.shared.u64 t, %1; cvt.u32.u64 %0, t; }" : "=r"(a) : "l"(p));
    return a;
}
__device__ __forceinline__ void cp16(uint32_t dst, const void* src) {
    asm volatile("cp.async.cg.shared.global [%0], [%1], 16;" :: "r"(dst), "l"(src));
}
__device__ __forceinline__ void ldsm4(uint32_t* r, uint32_t addr) {
    asm volatile("ldmatrix.sync.aligned.m8n8.x4.shared.b16 {%0,%1,%2,%3}, [%4];"
                 : "=r"(r[0]), "=r"(r[1]), "=r"(r[2]), "=r"(r[3]) : "r"(addr));
}
__device__ __forceinline__ void mma16816(float* c, const uint32_t* a, uint32_t b0, uint32_t b1) {
    asm volatile("mma.sync.aligned.m16n8k16.row.col.f32.bf16.bf16.f32 "
                 "{%0,%1,%2,%3},{%4,%5,%6,%7},{%8,%9},{%0,%1,%2,%3};"
                 : "+f"(c[0]), "+f"(c[1]), "+f"(c[2]), "+f"(c[3])
                 : "r"(a[0]), "r"(a[1]), "r"(a[2]), "r"(a[3]), "r"(b0), "r"(b1));
}

// 3-way bf16 split: x = hi + mid + lo (+ ~2^-27 rel)
__device__ __forceinline__ void s3(float x, __nv_bfloat16& a, __nv_bfloat16& b, __nv_bfloat16& c) {
    a = __float2bfloat16(x);
    float r = x - __bfloat162float(a);
    b = __float2bfloat16(r);
    c = __float2bfloat16(r - __bfloat162float(b));
}

// ---------------- small kernels ----------------
__global__ void split_k(const float* __restrict__ src, __nv_bfloat16* __restrict__ dst, size_t n) {
    size_t i = (size_t)blockIdx.x * blockDim.x + threadIdx.x;
    if (i >= n) return;
    __nv_bfloat16 h, m, l;
    s3(src[i], h, m, l);
    dst[i] = h; dst[i + n] = m; dst[i + 2 * n] = l;
}

// reorder LSTM weights to gate-quad order (n = 4*j+g) and split to planes
__global__ void prep_k(const float* __restrict__ Wih, const float* __restrict__ Whh,
                       const float* __restrict__ bih, const float* __restrict__ bhh) {
    int idx = blockIdx.x * blockDim.x + threadIdx.x;   // NG*HH
    int n = idx >> 9, k = idx & 511;
    int j = n >> 2, g = n & 3;
    int src = (g * 512 + j) * 512 + k;
    __nv_bfloat16 h, m, l;
    s3(Wih[src], h, m, l);
    g_WrP[idx] = h; g_WrP[idx + PS_W] = m; g_WrP[idx + 2 * PS_W] = l;
    s3(Whh[src], h, m, l);
    g_WhrP[idx] = h; g_WhrP[idx + PS_W] = m; g_WhrP[idx + 2 * PS_W] = l;
    if (k == 0) g_brb[n] = bih[g * 512 + j] + bhh[g * 512 + j];
}

__global__ void conv_k(const float* __restrict__ enc, const float* __restrict__ cw,
                       const float* __restrict__ cb) {
    int idx = blockIdx.x * blockDim.x + threadIdx.x;   // BN*HH
    int b = idx >> 9, hh = idx & 511;
    const float* e = enc + (size_t)b * TT * HH + hh;
    float s = cb[0];
#pragma unroll
    for (int t = 0; t < TT; t++) s += e[t * HH] * cw[t];
    __nv_bfloat16 h, m, l;
    s3(s, h, m, l);
    g_inp0P[idx] = h; g_inp0P[idx + PS_INP0] = m; g_inp0P[idx + 2 * PS_INP0] = l;
}

__global__ void init_k() {   // over 3*BN*HH
    size_t idx = (size_t)blockIdx.x * blockDim.x + threadIdx.x;
    g_hPA[idx] = __float2bfloat16(0.0f);
    if (idx < (size_t)BN * HH) g_c[idx] = 0.0f;
    if (idx < BN) { g_sel[idx] = 8; g_mask[idx] = 0; }
}

// ---------------- bf16x6 emulated fp32 GEMM via mma.sync ----------------
// C[m,n] = sum_k A[m,k]*W[n,k], K=512. CTA 128x128, k-chunk 64.
// smem: 6 plane tiles (A0,A1,A2,B0,B1,B2) each [128][128B] SW128 = 96KB.
// EPI==0: Out[dstrow(m)*ldo+n] = C + bias[n], dstrow=(m/grp)*rowmul+m%grp+rowoff
// EPI==1: fused LSTM cell vs g_P gate quads; update g_c; write h planes (houtP)
template <int EPI>
__global__ void __launch_bounds__(256, 2)
tgemm_k(const __nv_bfloat16* __restrict__ Ap, size_t APS,
        const __nv_bfloat16* __restrict__ Wp, size_t WPS,
        const float* __restrict__ bias,
        float* __restrict__ Out, int ldo,
        int grp, int rowmul, int rowoff,
        __nv_bfloat16* __restrict__ houtP) {
    extern __shared__ char smc[];
    uint32_t smb = smem_to_u32(smc);
    int tid = threadIdx.x, lane = tid & 31, wid = tid >> 5;
    int wm = wid >> 1, wn = wid & 1;
    int m0 = blockIdx.y * 128, n0 = blockIdx.x * 128;

    // ldmatrix lane patterns: row part + (column, swizzle-mask) kept separate.
    // Swizzle mask depends only on (row & 7); column (incl. k-step) is XORed per use.
    int la_r = lane & 15, la_c = (lane >> 4) * 16;          // A: rows 0-15, k halves
    uint32_t rowA = (uint32_t)(la_r * 128);
    uint32_t swA  = (uint32_t)((la_r & 7) << 4);
    int lb_r = (lane & 7) + ((lane >> 4) & 1) * 8;          // B: n rows, k halves
    int lb_c = ((lane >> 3) & 1) * 16;
    uint32_t rowB = (uint32_t)(lb_r * 128);
    uint32_t swB  = (uint32_t)((lb_r & 7) << 4);

    float c[2][8][4];
#pragma unroll
    for (int i = 0; i < 2; i++)
#pragma unroll
        for (int j = 0; j < 8; j++)
#pragma unroll
            for (int q = 0; q < 4; q++) c[i][j][q] = 0.0f;

    for (int kc = 0; kc < 8; kc++) {
        int kb = kc * 64;   // element offset in K
#pragma unroll
        for (int it = 0; it < 24; it++) {
            int g = tid + it * 256;
            int tile = g >> 10, rem = g & 1023, row = rem >> 3, c16 = rem & 7;
            const __nv_bfloat16* src;
            if (tile < 3)
                src = Ap + (size_t)tile * APS + (size_t)(m0 + row) * KK + kb + c16 * 8;
            else
                src = Wp + (size_t)(tile - 3) * WPS + (size_t)(n0 + row) * KK + kb + c16 * 8;
            uint32_t dst = smb + tile * 16384 + row * 128 + ((c16 * 16) ^ ((row & 7) << 4));
            cp16(dst, src);
        }
        asm volatile("cp.async.commit_group;");
        asm volatile("cp.async.wait_group 0;" ::: "memory");
        __syncthreads();

#pragma unroll
        for (int s = 0; s < 4; s++) {
            uint32_t a[3][2][4];
#pragma unroll
            for (int pl = 0; pl < 3; pl++)
#pragma unroll
                for (int mf = 0; mf < 2; mf++)
                    ldsm4(a[pl][mf],
                          smb + pl * 16384 + (wm * 32 + mf * 16) * 128 + rowA
                              + (((uint32_t)(la_c + s * 32)) ^ swA));
            const int pa[6] = {0, 2, 1, 0, 1, 0};
            const int pb[6] = {2, 0, 1, 1, 0, 0};
#pragma unroll
            for (int p = 0; p < 6; p++) {
#pragma unroll
                for (int n2 = 0; n2 < 4; n2++) {
                    uint32_t b[4];
                    ldsm4(b, smb + 49152 + pb[p] * 16384
                             + (wn * 64 + n2 * 16) * 128 + rowB
                             + (((uint32_t)(lb_c + s * 32)) ^ swB));
#pragma unroll
                    for (int mf = 0; mf < 2; mf++) {
                        mma16816(c[mf][n2 * 2],     a[pa[p]][mf], b[0], b[1]);
                        mma16816(c[mf][n2 * 2 + 1], a[pa[p]][mf], b[2], b[3]);
                    }
                }
            }
        }
        __syncthreads();
    }

    // stage C to smem (reuse plane region): stg[128][132] fp32
    float* stg = (float*)smc;
#pragma unroll
    for (int mf = 0; mf < 2; mf++)
#pragma unroll
        for (int nf = 0; nf < 8; nf++) {
            int r = wm * 32 + mf * 16 + (lane >> 2);
            int cc = wn * 64 + nf * 8 + (lane & 3) * 2;
            *(float2*)&stg[r * 132 + cc] = make_float2(c[mf][nf][0], c[mf][nf][1]);
            *(float2*)&stg[(r + 8) * 132 + cc] = make_float2(c[mf][nf][2], c[mf][nf][3]);
        }
    __syncthreads();

    if (EPI == 0) {
        int r = tid >> 1, cb = (tid & 1) * 64;
        int gr = m0 + r;
        int dr = (gr / grp) * rowmul + (gr % grp) + rowoff;
        float* op = Out + (size_t)dr * ldo + n0 + cb;
        const float* bp = bias + n0 + cb;
        const float* sr = stg + r * 132 + cb;
#pragma unroll
        for (int j = 0; j < 64; j += 4) {
            float4 v;
            v.x = sr[j] + bp[j];         v.y = sr[j + 1] + bp[j + 1];
            v.z = sr[j + 2] + bp[j + 2]; v.w = sr[j + 3] + bp[j + 3];
            *(float4*)(op + j) = v;
        }
    } else {
        int hl = tid & 15, rg = tid >> 4;
#pragma unroll
        for (int i = 0; i < 8; i++) {
            int row = rg * 8 + i, b = m0 + row;
            int sel = g_sel[b];
            const float* Pr = g_P + ((size_t)b * 9 + sel) * NG + n0;
#pragma unroll
            for (int half = 0; half < 2; half++) {
                const float* sr = stg + row * 132 + half * 64 + hl * 4;
                const float* pr = Pr + half * 64 + hl * 4;
                float gi = sr[0] + pr[0];
                float gf = sr[1] + pr[1];
                float gg = sr[2] + pr[2];
                float go = sr[3] + pr[3];
                int hidx = (n0 >> 2) + half * 16 + hl;
                size_t off = (size_t)b * HH + hidx;
                float co = g_c[off];
                float cn = sigm(gf) * co + sigm(gi) * tanhf(gg);
                float hv = sigm(go) * tanhf(cn);
                g_c[off] = cn;
                __nv_bfloat16 hh, hm, hlo;
                s3(hv, hh, hm, hlo);
                houtP[off] = hh;
                houtP[off + PS_H] = hm;
                houtP[off + 2 * PS_H] = hlo;
            }
        }
    }
}

// ---------------- fused attention step ----------------
__global__ void attn_k(const float* __restrict__ hw2,
                       const float* __restrict__ vw, const float* __restrict__ vb,
                       float* __restrict__ probs, float* __restrict__ ptrs, int step) {
    __shared__ float red[8][16];
    __shared__ float ui[8];
    int b = blockIdx.x, o = threadIdx.x;

    float hv = hw2[(size_t)b * HH + o];
    float tw = vw[o];
    float part[8];
    const float* we = g_W1E + (size_t)b * TT * HH + o;
#pragma unroll
    for (int t = 0; t < TT; t++) part[t] = tw * tanhf(we[t * HH] + hv);
#pragma unroll
    for (int off = 16; off > 0; off >>= 1)
#pragma unroll
        for (int t = 0; t < TT; t++) part[t] += __shfl_down_sync(0xffffffffu, part[t], off);
    if ((o & 31) == 0) {
        int w = o >> 5;
#pragma unroll
        for (int t = 0; t < TT; t++) red[t][w] = part[t];
    }
    __syncthreads();
    if (o < TT) {
        float s = 0.f;
#pragma unroll
        for (int w = 0; w < 16; w++) s += red[o][w];
        s += vb[0];
        ui[o] = s;
        probs[(size_t)b * (TT * TT) + step * TT + o] = s;
    }
    __syncthreads();
    if (o == 0) {
        int m = g_mask[b];
        int best = 0;
        float bv = -3.4e38f;
#pragma unroll
        for (int t = 0; t < TT; t++) {
            bool ok = ((m >> t) & 1) == 0;
            if (ok && ui[t] > bv) { bv = ui[t]; best = t; }
        }
        g_mask[b] = m | (1 << best);
        g_sel[b] = best;
        ptrs[(size_t)b * TT + step] = (float)best;
    }
}

// ---------------- launch ----------------
#define SMEM_BYTES 98304

extern "C" void kernel_launch(void* const* d_in, const int* in_sizes, int n_in,
                              void* d_out, int out_size) {
    const float* inps   = (const float*)d_in[0];
    const float* enc    = (const float*)d_in[1];
    const float* conv_w = (const float*)d_in[2];
    const float* conv_b = (const float*)d_in[3];
    const float* Wih    = (const float*)d_in[4];
    const float* Whh    = (const float*)d_in[5];
    const float* bih    = (const float*)d_in[6];
    const float* bhh    = (const float*)d_in[7];
    const float* W1     = (const float*)d_in[8];
    const float* b1     = (const float*)d_in[9];
    const float* W2     = (const float*)d_in[10];
    const float* b2     = (const float*)d_in[11];
    const float* vw     = (const float*)d_in[12];
    const float* vb     = (const float*)d_in[13];

    float* probs = (float*)d_out;
    float* ptrs  = probs + (size_t)BN * TT * TT;

    void *pP, *pW1E, *pbrb, *phw2;
    void *pencP, *pinpsP, *pinp0P, *pWrP, *pWhrP, *pW1P, *pW2P, *phPA, *phPB;
    cudaGetSymbolAddress(&pP,     g_P);
    cudaGetSymbolAddress(&pW1E,   g_W1E);
    cudaGetSymbolAddress(&pbrb,   g_brb);
    cudaGetSymbolAddress(&phw2,   g_hw2);
    cudaGetSymbolAddress(&pencP,  g_encP);
    cudaGetSymbolAddress(&pinpsP, g_inpsP);
    cudaGetSymbolAddress(&pinp0P, g_inp0P);
    cudaGetSymbolAddress(&pWrP,   g_WrP);
    cudaGetSymbolAddress(&pWhrP,  g_WhrP);
    cudaGetSymbolAddress(&pW1P,   g_W1P);
    cudaGetSymbolAddress(&pW2P,   g_W2P);
    cudaGetSymbolAddress(&phPA,   g_hPA);
    cudaGetSymbolAddress(&phPB,   g_hPB);

    cudaFuncSetAttribute(tgemm_k<0>, cudaFuncAttributeMaxDynamicSharedMemorySize, SMEM_BYTES);
    cudaFuncSetAttribute(tgemm_k<1>, cudaFuncAttributeMaxDynamicSharedMemorySize, SMEM_BYTES);

    // prep / splits
    prep_k<<<(NG * HH) / 256, 256>>>(Wih, Whh, bih, bhh);
    conv_k<<<(BN * HH) / 256, 256>>>(enc, conv_w, conv_b);
    init_k<<<(3 * BN * HH) / 256, 256>>>();
    split_k<<<(int)((PS_ENC + 255) / 256), 256>>>(enc,  (__nv_bfloat16*)pencP,  PS_ENC);
    split_k<<<(int)((PS_ENC + 255) / 256), 256>>>(inps, (__nv_bfloat16*)pinpsP, PS_ENC);
    split_k<<<(int)((PS_W1 + 255) / 256), 256>>>(W1, (__nv_bfloat16*)pW1P, PS_W1);
    split_k<<<(int)((PS_W1 + 255) / 256), 256>>>(W2, (__nv_bfloat16*)pW2P, PS_W1);

    // W1E = enc @ W1^T + b1   (M=32768, N=512)
    {
        dim3 g(HH / 128, (BN * TT) / 128);
        tgemm_k<0><<<g, 256, SMEM_BYTES>>>((const __nv_bfloat16*)pencP, PS_ENC,
                                           (const __nv_bfloat16*)pW1P, PS_W1,
                                           b1, (float*)pW1E, HH, 1, 1, 0, nullptr);
    }
    // P[b,t] = inps[b,t] @ Wr^T + brb   (M=32768, N=2048), dstrow=(r/8)*9 + r%8
    {
        dim3 g(NG / 128, (BN * TT) / 128);
        tgemm_k<0><<<g, 256, SMEM_BYTES>>>((const __nv_bfloat16*)pinpsP, PS_ENC,
                                           (const __nv_bfloat16*)pWrP, PS_W,
                                           (const float*)pbrb, (float*)pP, NG, 8, 9, 0, nullptr);
    }
    // P[b,8] = inp0 @ Wr^T + brb   (M=4096), dstrow = r*9 + 8
    {
        dim3 g(NG / 128, BN / 128);
        tgemm_k<0><<<g, 256, SMEM_BYTES>>>((const __nv_bfloat16*)pinp0P, PS_INP0,
                                           (const __nv_bfloat16*)pWrP, PS_W,
                                           (const float*)pbrb, (float*)pP, NG, 1, 9, 8, nullptr);
    }

    // 8 decode steps
    for (int s = 0; s < TT; s++) {
        const __nv_bfloat16* hin = (s & 1) ? (const __nv_bfloat16*)phPB
                                           : (const __nv_bfloat16*)phPA;
        __nv_bfloat16* hout = (s & 1) ? (__nv_bfloat16*)phPA : (__nv_bfloat16*)phPB;
        {
            dim3 g(NG / 128, BN / 128);
            tgemm_k<1><<<g, 256, SMEM_BYTES>>>(hin, PS_H,
                                               (const __nv_bfloat16*)pWhrP, PS_W,
                                               nullptr, nullptr, 0, 1, 1, 0, hout);
        }
        {
            dim3 g(HH / 128, BN / 128);
            tgemm_k<0><<<g, 256, SMEM_BYTES>>>((const __nv_bfloat16*)hout, PS_H,
                                               (const __nv_bfloat16*)pW2P, PS_W1,
                                               b2, (float*)phw2, HH, 1, 1, 0, nullptr);
        }
        attn_k<<<BN, HH>>>((const float*)phw2, vw, vb, probs, ptrs, s);
    }
}